// round 10
// baseline (speedup 1.0000x reference)
#include <cuda_runtime.h>
#include <cuda_bf16.h>

#define NPTS    500000
#define C_OUT   64
#define GRID_H  256
#define GRID_W  256
#define NCELL   (GRID_H * GRID_W)
#define BLK     256
#define NTH     512
#define NBLK    ((NPTS + BLK - 1) / BLK)
#define KC      26              // 8 chunks * 26 = 208
#define HP      264             // padded point-stride for H

// shared float offsets
#define OW1  0            // 208*64 = 13312
#define OW2D 13312        // 64*128 (dup) = 8192
#define OXD  21504        // 26*512 = 13312 (X duplicated pairs)
#define OH   34816        // 64*264 = 16896
#define OB1  51712
#define OG   51776
#define OB   51840
#define OB2  51904
#define OMP  51968        // 64 float2 (freq, phase)
#define OFL  52096        // 256 ints
#define SMF  52352
#define SMB  (SMF * 4)    // 209408 B -> 1 CTA/SM

__device__ float g_accum[NCELL * C_OUT];   // cell-major scratch [cell][ch]
__device__ float g_counts[NCELL];

__device__ __forceinline__ void fma2(unsigned long long& d, unsigned long long a,
                                     unsigned long long b) {
    asm("fma.rn.f32x2 %0, %1, %2, %0;" : "+l"(d) : "l"(a), "l"(b));
}
__device__ __forceinline__ float2 up2(unsigned long long a) {
    float2 r; asm("mov.b64 {%0, %1}, %2;" : "=f"(r.x), "=f"(r.y) : "l"(a)); return r;
}
__device__ __forceinline__ void red4(float* p, float a, float b, float c, float d) {
    asm volatile("red.global.add.v4.f32 [%0], {%1, %2, %3, %4};"
                 :: "l"(p), "f"(a), "f"(b), "f"(c), "f"(d) : "memory");
}

__global__ void dummy_kernel() {}

__global__ __launch_bounds__(NTH, 1)
void p2g_kernel(const float* __restrict__ pos,
                const float* __restrict__ feat,
                const float* __restrict__ W1,
                const float* __restrict__ b1,
                const float* __restrict__ lng,
                const float* __restrict__ lnb,
                const float* __restrict__ W2,
                const float* __restrict__ b2,
                const int*   __restrict__ ax1p,
                const int*   __restrict__ ax2p) {
    extern __shared__ float sm[];
    int* sFlat = (int*)&sm[OFL];
    const int tid  = threadIdx.x;
    const int base = blockIdx.x * BLK;

    // ---- stage weights + tables ----
    {
        const float4* w1v = (const float4*)W1;
        float4* d1 = (float4*)&sm[OW1];
#pragma unroll
        for (int i = 0; i < 6; ++i) d1[tid + i * NTH] = w1v[tid + i * NTH];
        if (tid < 3328 - 6 * NTH) d1[tid + 6 * NTH] = w1v[tid + 6 * NTH];

        // W2 duplicated: [k][2c] = [k][2c+1] = W2[k][c]
#pragma unroll
        for (int i = 0; i < 8; ++i) {
            int e = tid + i * NTH;               // 0..4095
            float v = W2[e];
            int k = e >> 6, c = e & 63;
            *(float2*)&sm[OW2D + k * 128 + 2 * c] = make_float2(v, v);
        }
        if (tid < 64) {
            int f = tid & 31, t = tid >> 5;
            sm[OMP + 2 * tid]     = exp2f((float)f * 0.03125f) * 1.57079632679489662f;
            sm[OMP + 2 * tid + 1] = t ? 1.57079632679489662f : 0.0f;
            sm[OB1 + tid] = b1[tid];
            sm[OG  + tid] = lng[tid];
            sm[OB  + tid] = lnb[tid];
            sm[OB2 + tid] = b2[tid];
        }
    }

    // ---- per-point data: 2 threads per point ----
    const int p    = tid & 255;
    const int pg   = min(base + p, NPTS - 1);
    const int half = tid >> 8;
    float pd0 = pos[pg * 3 + 0];
    float pd1 = pos[pg * 3 + 1];
    float pd2 = pos[pg * 3 + 2];
    float fr[16];
    {
        const float4* fv = (const float4*)(feat + pg * 16);
#pragma unroll
        for (int i = 0; i < 4; ++i) {
            float4 t = fv[i];
            fr[4 * i + 0] = t.x; fr[4 * i + 1] = t.y;
            fr[4 * i + 2] = t.z; fr[4 * i + 3] = t.w;
        }
    }
    if (tid < 256) {
        int a1 = *ax1p, a2 = *ax2p;
        float v1 = (a1 == 0) ? pd0 : ((a1 == 1) ? pd1 : pd2);
        float v2 = (a2 == 0) ? pd0 : ((a2 == 1) ? pd1 : pd2);
        float n1 = fminf(fmaxf((v1 + 1.0f) * 0.5f, 0.0f), 1.0f);
        float n2 = fminf(fmaxf((v2 + 1.0f) * 0.5f, 0.0f), 1.0f);
        int i1 = min(max((int)floorf(n1 * (float)GRID_H), 0), GRID_H - 1);
        int i2 = min(max((int)floorf(n2 * (float)GRID_W), 0), GRID_W - 1);
        sFlat[tid] = i1 * GRID_W + i2;
    }

    const int opt = tid >> 2;     // 0..127 : points 2*opt, 2*opt+1
    const int chg = tid & 3;      // 0..3   : channels chg*16 .. +15

    unsigned long long acc[2][8];   // [pt][chpair] = 32 floats
#pragma unroll
    for (int a = 0; a < 2; ++a)
#pragma unroll
        for (int b = 0; b < 8; ++b) acc[a][b] = 0ull;

    __syncthreads();

    // ================= GEMM1: 8 chunks of K=26 =================
#pragma unroll 1
    for (int c = 0; c < 8; ++c) {
        const int k0 = c * KC;
        // build own point's X rows (split between the two threads), dup pairs
#pragma unroll 1
        for (int i = half; i < KC; i += 2) {
            int k = k0 + i;
            float v;
            if (k < 16) {
                v = fr[k];
            } else {
                int j = k - 16;
                float pdx = (j < 64) ? pd0 : ((j < 128) ? pd1 : pd2);
                float2 mp = *(const float2*)&sm[OMP + 2 * (j & 63)];
                v = __sinf(fmaf(pdx, mp.x, mp.y));
            }
            *(float2*)&sm[OXD + i * 512 + 2 * p] = make_float2(v, v);
        }
        __syncthreads();

#pragma unroll
        for (int i = 0; i < KC; ++i) {
            ulonglong2 xv = *(const ulonglong2*)&sm[OXD + i * 512 + 4 * opt];
            unsigned long long xp[2] = {xv.x, xv.y};   // dup(p0), dup(p1)
            const float* wr = &sm[OW1 + (k0 + i) * 64 + chg * 16];
            ulonglong2 w0 = *(const ulonglong2*)wr;
            ulonglong2 w1 = *(const ulonglong2*)(wr + 4);
            ulonglong2 w2 = *(const ulonglong2*)(wr + 8);
            ulonglong2 w3 = *(const ulonglong2*)(wr + 12);
            unsigned long long wp[8] = {w0.x, w0.y, w1.x, w1.y,
                                        w2.x, w2.y, w3.x, w3.y};
#pragma unroll
            for (int a = 0; a < 2; ++a)
#pragma unroll
                for (int b = 0; b < 8; ++b) fma2(acc[a][b], xp[a], wp[b]);
        }
        __syncthreads();
    }

    // ---- bias + LayerNorm + exact GELU (4 threads per point, shfl 1,2) ----
    {
        float h[2][16];
#pragma unroll
        for (int a = 0; a < 2; ++a)
#pragma unroll
            for (int cp = 0; cp < 8; ++cp) {
                float2 t = up2(acc[a][cp]);
                h[a][2 * cp]     = t.x + sm[OB1 + chg * 16 + 2 * cp];
                h[a][2 * cp + 1] = t.y + sm[OB1 + chg * 16 + 2 * cp + 1];
            }
        float s[2], s2[2];
#pragma unroll
        for (int a = 0; a < 2; ++a) {
            s[a] = 0.0f; s2[a] = 0.0f;
#pragma unroll
            for (int j = 0; j < 16; ++j) { s[a] += h[a][j]; s2[a] += h[a][j] * h[a][j]; }
        }
#pragma unroll
        for (int o = 1; o < 4; o <<= 1) {
#pragma unroll
            for (int a = 0; a < 2; ++a) {
                s[a]  += __shfl_xor_sync(0xFFFFFFFF, s[a],  o);
                s2[a] += __shfl_xor_sync(0xFFFFFFFF, s2[a], o);
            }
        }
#pragma unroll
        for (int a = 0; a < 2; ++a) {
            float mu   = s[a] * (1.0f / 64.0f);
            float var  = s2[a] * (1.0f / 64.0f) - mu * mu;
            float rstd = rsqrtf(var + 1e-5f);
#pragma unroll
            for (int j = 0; j < 16; ++j) {
                float v = (h[a][j] - mu) * rstd * sm[OG + chg * 16 + j]
                          + sm[OB + chg * 16 + j];
                h[a][j] = 0.5f * v * (1.0f + erff(v * 0.70710678118654752f));
            }
        }
        // store H [ch][pt] (points of this thread are adjacent -> float2)
#pragma unroll
        for (int j = 0; j < 16; ++j) {
            int ch = chg * 16 + j;
            *(float2*)&sm[OH + ch * HP + 2 * opt] = make_float2(h[0][j], h[1][j]);
        }
    }
    __syncthreads();

    // ================= GEMM2: x = natural point pair, w = pre-dup'd ==========
    unsigned long long a2[16];     // [ch j] -> (p0, p1)
#pragma unroll
    for (int j = 0; j < 16; ++j) a2[j] = 0ull;

#pragma unroll 8
    for (int k = 0; k < 64; ++k) {
        unsigned long long xv = *(const unsigned long long*)&sm[OH + k * HP + 2 * opt];
        const ulonglong2* wr = (const ulonglong2*)&sm[OW2D + k * 128 + chg * 32];
#pragma unroll
        for (int q = 0; q < 8; ++q) {
            ulonglong2 w = wr[q];
            fma2(a2[2 * q],     xv, w.x);
            fma2(a2[2 * q + 1], xv, w.y);
        }
    }

    // ---- scatter: red.v4 into cell-major scratch ----
    float bias[16];
#pragma unroll
    for (int j = 0; j < 16; ++j) bias[j] = sm[OB2 + chg * 16 + j];

#pragma unroll
    for (int pl = 0; pl < 2; ++pl) {
        int pLoc = 2 * opt + pl;
        if (base + pLoc < NPTS) {
            int fl = sFlat[pLoc];
            float* dst = &g_accum[fl * 64 + chg * 16];
#pragma unroll
            for (int q = 0; q < 4; ++q) {
                float2 t0 = up2(a2[4 * q + 0]);
                float2 t1 = up2(a2[4 * q + 1]);
                float2 t2 = up2(a2[4 * q + 2]);
                float2 t3 = up2(a2[4 * q + 3]);
                float v0 = (pl ? t0.y : t0.x) + bias[4 * q + 0];
                float v1 = (pl ? t1.y : t1.x) + bias[4 * q + 1];
                float v2 = (pl ? t2.y : t2.x) + bias[4 * q + 2];
                float v3 = (pl ? t3.y : t3.x) + bias[4 * q + 3];
                red4(dst + 4 * q, v0, v1, v2, v3);
            }
            if (chg == 0) atomicAdd(&g_counts[fl], 1.0f);
        }
    }
}

// transpose [cell][ch] -> [ch][cell], mean-divide, re-zero scratch
__global__ __launch_bounds__(256)
void finalize_kernel(float* __restrict__ out) {
    __shared__ float tile[64][65];
    __shared__ float cnt[64];
    const int tid = threadIdx.x;
    const int cell0 = blockIdx.x * 64;

#pragma unroll
    for (int it = 0; it < 4; ++it) {
        int lin = it * 256 + tid;
        float4* src = (float4*)&g_accum[cell0 * 64] + lin;
        float4 v = *src;
        int row = lin >> 4, col4 = (lin & 15) * 4;
        tile[row][col4 + 0] = v.x;
        tile[row][col4 + 1] = v.y;
        tile[row][col4 + 2] = v.z;
        tile[row][col4 + 3] = v.w;
        *src = make_float4(0.0f, 0.0f, 0.0f, 0.0f);
    }
    if (tid < 64) {
        cnt[tid] = 1.0f / fmaxf(g_counts[cell0 + tid], 1.0f);
        g_counts[cell0 + tid] = 0.0f;
    }
    __syncthreads();

#pragma unroll
    for (int it = 0; it < 4; ++it) {
        int lin = it * 256 + tid;
        int ch = lin >> 4, cl4 = (lin & 15) * 4;
        float4 o;
        o.x = tile[cl4 + 0][ch] * cnt[cl4 + 0];
        o.y = tile[cl4 + 1][ch] * cnt[cl4 + 1];
        o.z = tile[cl4 + 2][ch] * cnt[cl4 + 2];
        o.w = tile[cl4 + 3][ch] * cnt[cl4 + 3];
        *(float4*)&out[ch * NCELL + cell0 + cl4] = o;
    }
}

extern "C" void kernel_launch(void* const* d_in, const int* in_sizes, int n_in,
                              void* d_out, int out_size) {
    const float* pos  = (const float*)d_in[0];
    const float* feat = (const float*)d_in[1];
    const float* W1   = (const float*)d_in[2];
    const float* b1   = (const float*)d_in[3];
    const float* lng  = (const float*)d_in[4];
    const float* lnb  = (const float*)d_in[5];
    const float* W2   = (const float*)d_in[6];
    const float* b2   = (const float*)d_in[7];
    const int*   ax1  = (const int*)d_in[8];
    const int*   ax2  = (const int*)d_in[9];
    float* out = (float*)d_out;

    cudaFuncSetAttribute(p2g_kernel, cudaFuncAttributeMaxDynamicSharedMemorySize, SMB);

    // Launch pattern d,p,f,d: period 4 puts p2g at global launch #6, which is
    // the launch ncu's "-s 5 -c 1" captures -> we finally profile the hot kernel.
    dummy_kernel<<<1, 32>>>();
    p2g_kernel<<<NBLK, NTH, SMB>>>(pos, feat, W1, b1, lng, lnb, W2, b2, ax1, ax2);
    finalize_kernel<<<NCELL / 64, 256>>>(out);
    dummy_kernel<<<1, 32>>>();
}

// round 11
// speedup vs baseline: 2.9286x; 2.9286x over previous
#include <cuda_runtime.h>
#include <cuda_bf16.h>

#define NPTS    500000
#define C_OUT   64
#define GRID_H  256
#define GRID_W  256
#define NCELL   (GRID_H * GRID_W)
#define BLK     256
#define NTH     256
#define NBLK    ((NPTS + BLK - 1) / BLK)
#define KC      26              // 8 chunks * 26 = 208
#define HP      260             // padded point-stride for H (260 % 32 == 4)
#define XBUF    (KC * 256)      // 6656 floats per X buffer

// shared float offsets
#define OW1D 0            // 208*128 (dup, q-major swizzle) = 26624
#define OX   26624        // 2 * 6656 = 13312 (double-buffered X)
#define OH   26624        // 64*260 = 16640 (overlaps OX; used after GEMM1)
#define OW2D 43264        // 64*128 (dup, q-major swizzle) = 8192
#define OB1  51456
#define OG   51520
#define OB   51584
#define OB2  51648
#define OMP  51712        // 64 float2 (freq, phase) = 128
#define OFL  51840        // 256 ints
#define SMF  52096
#define SMB  (SMF * 4)    // 208384 B -> 1 CTA/SM

__device__ float g_accum[NCELL * C_OUT];   // cell-major scratch [cell][ch]
__device__ float g_counts[NCELL];

__device__ __forceinline__ void fma2(unsigned long long& d, unsigned long long a,
                                     unsigned long long b) {
    asm("fma.rn.f32x2 %0, %1, %2, %0;" : "+l"(d) : "l"(a), "l"(b));
}
__device__ __forceinline__ float2 up2(unsigned long long a) {
    float2 r; asm("mov.b64 {%0, %1}, %2;" : "=f"(r.x), "=f"(r.y) : "l"(a)); return r;
}
__device__ __forceinline__ void red4(float* p, float a, float b, float c, float d) {
    asm volatile("red.global.add.v4.f32 [%0], {%1, %2, %3, %4};"
                 :: "l"(p), "f"(a), "f"(b), "f"(c), "f"(d) : "memory");
}
__device__ __forceinline__ void red1(float* p, float v) {
    asm volatile("red.global.add.f32 [%0], %1;" :: "l"(p), "f"(v) : "memory");
}

__global__ void dummy_kernel() {}

// dup'd weight staging with q-major swizzle:
// channel c of row k lands at word  k*128 + ((c&7)>>1)*32 + (c>>3)*4 + (c&1)*2
// so a thread with chg = tid&7 reads its 8 dup'd channels as 4 conflict-free
// LDS.128 at offsets chg*4 + {0,32,64,96}.
__device__ __forceinline__ int wswz(int k, int c) {
    return k * 128 + ((c & 7) >> 1) * 32 + (c >> 3) * 4 + (c & 1) * 2;
}

__global__ __launch_bounds__(NTH, 1)
void p2g_kernel(const float* __restrict__ pos,
                const float* __restrict__ feat,
                const float* __restrict__ W1,
                const float* __restrict__ b1,
                const float* __restrict__ lng,
                const float* __restrict__ lnb,
                const float* __restrict__ W2,
                const float* __restrict__ b2,
                const int*   __restrict__ ax1p,
                const int*   __restrict__ ax2p) {
    extern __shared__ float sm[];
    int* sFlat = (int*)&sm[OFL];
    const int tid  = threadIdx.x;
    const int base = blockIdx.x * BLK;

    // ---- stage dup'd weights + tables ----
    {
#pragma unroll
        for (int i = 0; i < 52; ++i) {
            int e = i * 256 + tid;               // 0..13311
            float v = W1[e];
            *(float2*)&sm[OW1D + wswz(e >> 6, e & 63)] = make_float2(v, v);
        }
#pragma unroll
        for (int i = 0; i < 16; ++i) {
            int e = i * 256 + tid;               // 0..4095
            float v = W2[e];
            *(float2*)&sm[OW2D + wswz(e >> 6, e & 63)] = make_float2(v, v);
        }
        if (tid < 64) {
            int f = tid & 31, t = tid >> 5;
            sm[OMP + 2 * tid]     = exp2f((float)f * 0.03125f) * 1.57079632679489662f;
            sm[OMP + 2 * tid + 1] = t ? 1.57079632679489662f : 0.0f;
            sm[OB1 + tid] = b1[tid];
            sm[OG  + tid] = lng[tid];
            sm[OB  + tid] = lnb[tid];
            sm[OB2 + tid] = b2[tid];
        }
    }

    // ---- per-thread point ----
    const int pg = min(base + tid, NPTS - 1);
    float pd0 = pos[pg * 3 + 0];
    float pd1 = pos[pg * 3 + 1];
    float pd2 = pos[pg * 3 + 2];
    float fr[16];
    {
        const float4* fv = (const float4*)(feat + pg * 16);
#pragma unroll
        for (int i = 0; i < 4; ++i) {
            float4 t = fv[i];
            fr[4 * i + 0] = t.x; fr[4 * i + 1] = t.y;
            fr[4 * i + 2] = t.z; fr[4 * i + 3] = t.w;
        }
    }
    {
        int a1 = *ax1p, a2 = *ax2p;
        float v1 = (a1 == 0) ? pd0 : ((a1 == 1) ? pd1 : pd2);
        float v2 = (a2 == 0) ? pd0 : ((a2 == 1) ? pd1 : pd2);
        float n1 = fminf(fmaxf((v1 + 1.0f) * 0.5f, 0.0f), 1.0f);
        float n2 = fminf(fmaxf((v2 + 1.0f) * 0.5f, 0.0f), 1.0f);
        int i1 = min(max((int)floorf(n1 * (float)GRID_H), 0), GRID_H - 1);
        int i2 = min(max((int)floorf(n2 * (float)GRID_W), 0), GRID_W - 1);
        sFlat[tid] = i1 * GRID_W + i2;
    }

    const int ptg = tid >> 3;   // 0..31 : points ptg*8 .. +7 (4 natural pairs)
    const int chg = tid & 7;    // 0..7  : channels chg*8 .. +7

    unsigned long long acc[4][8];   // [pt-pair][ch] = 8 pts x 8 ch
#pragma unroll
    for (int a = 0; a < 4; ++a)
#pragma unroll
        for (int b = 0; b < 8; ++b) acc[a][b] = 0ull;

    __syncthreads();

    // ---- build X chunk 0 (contains the 16 features + first PE rows) ----
#pragma unroll 1
    for (int i = 0; i < KC; ++i) {
        float v;
        if (i < 16) {
            v = fr[i];
        } else {
            int j = i - 16;                      // 0..9 -> dim 0
            float2 mp = *(const float2*)&sm[OMP + 2 * j];
            v = __sinf(fmaf(pd0, mp.x, mp.y));
        }
        sm[OX + i * 256 + tid] = v;
    }
    __syncthreads();

    // ================= GEMM1: double-buffered chunks =================
#pragma unroll 1
    for (int c = 0; c < 8; ++c) {
        // build chunk c+1 into the other buffer (issues sins under the GEMM)
        if (c < 7) {
            const int k0 = (c + 1) * KC - 16;    // PE index of row 0
            float* xb = &sm[OX + ((c + 1) & 1) * XBUF];
#pragma unroll 1
            for (int i = 0; i < KC; ++i) {
                int j = k0 + i;                  // >= 10, pure PE
                float pdx = (j < 64) ? pd0 : ((j < 128) ? pd1 : pd2);
                float2 mp = *(const float2*)&sm[OMP + 2 * (j & 63)];
                xb[i * 256 + tid] = __sinf(fmaf(pdx, mp.x, mp.y));
            }
        }
        // GEMM on chunk c
        const float* xc = &sm[OX + (c & 1) * XBUF];
        const int kb = c * KC;
#pragma unroll
        for (int i = 0; i < KC; ++i) {
            const float* xr = &xc[i * 256 + ptg * 8];
            ulonglong2 xa = *(const ulonglong2*)xr;        // (p0,p1),(p2,p3)
            ulonglong2 xb2 = *(const ulonglong2*)(xr + 4); // (p4,p5),(p6,p7)
            unsigned long long xp[4] = {xa.x, xa.y, xb2.x, xb2.y};
            const float* wr = &sm[OW1D + (kb + i) * 128 + chg * 4];
            ulonglong2 w0 = *(const ulonglong2*)(wr);
            ulonglong2 w1 = *(const ulonglong2*)(wr + 32);
            ulonglong2 w2 = *(const ulonglong2*)(wr + 64);
            ulonglong2 w3 = *(const ulonglong2*)(wr + 96);
            unsigned long long wb[8] = {w0.x, w0.y, w1.x, w1.y,
                                        w2.x, w2.y, w3.x, w3.y};
#pragma unroll
            for (int a = 0; a < 4; ++a)
#pragma unroll
                for (int b = 0; b < 8; ++b) fma2(acc[a][b], xp[a], wb[b]);
        }
        __syncthreads();
    }

    // ---- write H = h + b1 (layout [ch][pt], stride HP), reset acc ----
#pragma unroll
    for (int b = 0; b < 8; ++b) {
        int ch = chg * 8 + b;
        float bb = sm[OB1 + ch];
        float2 v0 = up2(acc[0][b]), v1 = up2(acc[1][b]);
        float2 v2 = up2(acc[2][b]), v3 = up2(acc[3][b]);
        float4 o0 = {v0.x + bb, v0.y + bb, v1.x + bb, v1.y + bb};
        float4 o1 = {v2.x + bb, v2.y + bb, v3.x + bb, v3.y + bb};
        *(float4*)&sm[OH + ch * HP + ptg * 8]     = o0;
        *(float4*)&sm[OH + ch * HP + ptg * 8 + 4] = o1;
        acc[0][b] = acc[1][b] = acc[2][b] = acc[3][b] = 0ull;
    }
    __syncthreads();

    // ---- LayerNorm + exact GELU: thread tid owns point tid ----
    {
        float s = 0.0f, s2 = 0.0f;
#pragma unroll 8
        for (int cc = 0; cc < 64; ++cc) {
            float v = sm[OH + cc * HP + tid];
            s += v; s2 += v * v;
        }
        float mu   = s * (1.0f / 64.0f);
        float var  = s2 * (1.0f / 64.0f) - mu * mu;
        float rstd = rsqrtf(var + 1e-5f);
#pragma unroll 8
        for (int cc = 0; cc < 64; ++cc) {
            float v = sm[OH + cc * HP + tid];
            v = (v - mu) * rstd * sm[OG + cc] + sm[OB + cc];
            v = 0.5f * v * (1.0f + erff(v * 0.70710678118654752f));
            sm[OH + cc * HP + tid] = v;
        }
    }
    __syncthreads();

    // ================= GEMM2: same tiling, dup'd W2 =================
#pragma unroll 8
    for (int k = 0; k < 64; ++k) {
        const float* xr = &sm[OH + k * HP + ptg * 8];
        ulonglong2 xa = *(const ulonglong2*)xr;
        ulonglong2 xb2 = *(const ulonglong2*)(xr + 4);
        unsigned long long xp[4] = {xa.x, xa.y, xb2.x, xb2.y};
        const float* wr = &sm[OW2D + k * 128 + chg * 4];
        ulonglong2 w0 = *(const ulonglong2*)(wr);
        ulonglong2 w1 = *(const ulonglong2*)(wr + 32);
        ulonglong2 w2 = *(const ulonglong2*)(wr + 64);
        ulonglong2 w3 = *(const ulonglong2*)(wr + 96);
        unsigned long long wb[8] = {w0.x, w0.y, w1.x, w1.y,
                                    w2.x, w2.y, w3.x, w3.y};
#pragma unroll
        for (int a = 0; a < 4; ++a)
#pragma unroll
            for (int b = 0; b < 8; ++b) fma2(acc[a][b], xp[a], wb[b]);
    }

    // ---- scatter: red.v4 into cell-major scratch ----
    float bias[8];
#pragma unroll
    for (int b = 0; b < 8; ++b) bias[b] = sm[OB2 + chg * 8 + b];

#pragma unroll
    for (int pl = 0; pl < 8; ++pl) {
        int pG = base + ptg * 8 + pl;
        if (pG < NPTS) {
            int fl = sFlat[ptg * 8 + pl];
            float* dst = &g_accum[fl * 64 + chg * 8];
            int pr = pl >> 1;
            bool hi = pl & 1;
            float v[8];
#pragma unroll
            for (int b = 0; b < 8; ++b) {
                float2 t = up2(acc[pr][b]);
                v[b] = (hi ? t.y : t.x) + bias[b];
            }
            red4(dst,     v[0], v[1], v[2], v[3]);
            red4(dst + 4, v[4], v[5], v[6], v[7]);
            if (chg == 0) red1(&g_counts[fl], 1.0f);
        }
    }
}

// transpose [cell][ch] -> [ch][cell], mean-divide, re-zero scratch
__global__ __launch_bounds__(256)
void finalize_kernel(float* __restrict__ out) {
    __shared__ float tile[64][65];
    __shared__ float cnt[64];
    const int tid = threadIdx.x;
    const int cell0 = blockIdx.x * 64;

#pragma unroll
    for (int it = 0; it < 4; ++it) {
        int lin = it * 256 + tid;
        float4* src = (float4*)&g_accum[cell0 * 64] + lin;
        float4 v = *src;
        int row = lin >> 4, col4 = (lin & 15) * 4;
        tile[row][col4 + 0] = v.x;
        tile[row][col4 + 1] = v.y;
        tile[row][col4 + 2] = v.z;
        tile[row][col4 + 3] = v.w;
        *src = make_float4(0.0f, 0.0f, 0.0f, 0.0f);
    }
    if (tid < 64) {
        cnt[tid] = 1.0f / fmaxf(g_counts[cell0 + tid], 1.0f);
        g_counts[cell0 + tid] = 0.0f;
    }
    __syncthreads();

#pragma unroll
    for (int it = 0; it < 4; ++it) {
        int lin = it * 256 + tid;
        int ch = lin >> 4, cl4 = (lin & 15) * 4;
        float4 o;
        o.x = tile[cl4 + 0][ch] * cnt[cl4 + 0];
        o.y = tile[cl4 + 1][ch] * cnt[cl4 + 1];
        o.z = tile[cl4 + 2][ch] * cnt[cl4 + 2];
        o.w = tile[cl4 + 3][ch] * cnt[cl4 + 3];
        *(float4*)&out[ch * NCELL + cell0 + cl4] = o;
    }
}

extern "C" void kernel_launch(void* const* d_in, const int* in_sizes, int n_in,
                              void* d_out, int out_size) {
    const float* pos  = (const float*)d_in[0];
    const float* feat = (const float*)d_in[1];
    const float* W1   = (const float*)d_in[2];
    const float* b1   = (const float*)d_in[3];
    const float* lng  = (const float*)d_in[4];
    const float* lnb  = (const float*)d_in[5];
    const float* W2   = (const float*)d_in[6];
    const float* b2   = (const float*)d_in[7];
    const int*   ax1  = (const int*)d_in[8];
    const int*   ax2  = (const int*)d_in[9];
    float* out = (float*)d_out;

    cudaFuncSetAttribute(p2g_kernel, cudaFuncAttributeMaxDynamicSharedMemorySize, SMB);

    // Pattern (p2g, finalize, dummy): captured launch position is ≡ 4 (mod period)
    // across all observed rounds; 4 mod 3 == 1 -> ncu profiles p2g_kernel.
    p2g_kernel<<<NBLK, NTH, SMB>>>(pos, feat, W1, b1, lng, lnb, W2, b2, ax1, ax2);
    finalize_kernel<<<NCELL / 64, 256>>>(out);
    dummy_kernel<<<1, 32>>>();
}

// round 14
// speedup vs baseline: 3.3090x; 1.1299x over previous
#include <cuda_runtime.h>
#include <cuda_bf16.h>

#define NPTS    500000
#define C_OUT   64
#define GRID_H  256
#define GRID_W  256
#define NCELL   (GRID_H * GRID_W)
#define BLK     128                 // points per CTA
#define NTH     128
#define NTILE   3907                // ceil(500000 / 128)
#define PGRID   296                 // 2 CTAs per SM, persistent
#define KC      13                  // 16 chunks * 13 = 208
#define HP      68                  // padded channel-stride for H [pt][ch]

// shared float offsets
#define OW1  0            // 208*64 = 13312
#define OW2  13312        // 64*64  = 4096
#define OXH  17408        // union: X dup 2*13*256=6656  |  H 128*68=8704
#define OB1  26112
#define OG   26176
#define OB   26240
#define OB2  26304
#define OMP  26368        // 64 float2 (freq, phase) = 128
#define OFL  26496        // 128 ints
#define SMF  26624
#define SMB  (SMF * 4)    // 106496 B -> 2 CTAs/SM

#define OX0  OXH
#define OX1  (OXH + KC * 256)
#define OH   OXH

__device__ float g_accum[NCELL * C_OUT];   // cell-major scratch [cell][ch]
__device__ float g_counts[NCELL];

__device__ __forceinline__ void fma2(unsigned long long& d, unsigned long long a,
                                     unsigned long long b) {
    asm("fma.rn.f32x2 %0, %1, %2, %0;" : "+l"(d) : "l"(a), "l"(b));
}
__device__ __forceinline__ unsigned long long dup2(float v) {
    unsigned long long r; asm("mov.b64 %0, {%1, %1};" : "=l"(r) : "f"(v)); return r;
}
__device__ __forceinline__ float2 up2(unsigned long long a) {
    float2 r; asm("mov.b64 {%0, %1}, %2;" : "=f"(r.x), "=f"(r.y) : "l"(a)); return r;
}
__device__ __forceinline__ void red4(float* p, float a, float b, float c, float d) {
    asm volatile("red.global.add.v4.f32 [%0], {%1, %2, %3, %4};"
                 :: "l"(p), "f"(a), "f"(b), "f"(c), "f"(d) : "memory");
}
__device__ __forceinline__ void red1(float* p, float v) {
    asm volatile("red.global.add.f32 [%0], %1;" :: "l"(p), "f"(v) : "memory");
}

__global__ void dummy_kernel() {}

__global__ __launch_bounds__(NTH)
void p2g_kernel(const float* __restrict__ pos,
                const float* __restrict__ feat,
                const float* __restrict__ W1,
                const float* __restrict__ b1,
                const float* __restrict__ lng,
                const float* __restrict__ lnb,
                const float* __restrict__ W2,
                const float* __restrict__ b2,
                const int*   __restrict__ ax1p,
                const int*   __restrict__ ax2p) {
    extern __shared__ float sm[];
    int* sFlat = (int*)&sm[OFL];
    const int tid = threadIdx.x;

    // ---- stage weights + tables once (persistent CTA) ----
    {
        const float4* w1v = (const float4*)W1;
        float4* d1 = (float4*)&sm[OW1];
#pragma unroll
        for (int i = 0; i < 26; ++i) d1[tid + i * NTH] = w1v[tid + i * NTH];
        const float4* w2v = (const float4*)W2;
        float4* d2 = (float4*)&sm[OW2];
#pragma unroll
        for (int i = 0; i < 8; ++i) d2[tid + i * NTH] = w2v[tid + i * NTH];
        if (tid < 64) {
            int f = tid & 31, t = tid >> 5;
            sm[OMP + 2 * tid]     = exp2f((float)f * 0.03125f) * 1.57079632679489662f;
            sm[OMP + 2 * tid + 1] = t ? 1.57079632679489662f : 0.0f;
            sm[OB1 + tid] = b1[tid];
            sm[OG  + tid] = lng[tid];
            sm[OB  + tid] = lnb[tid];
            sm[OB2 + tid] = b2[tid];
        }
    }
    const int ax1 = *ax1p, ax2 = *ax2p;

    const int ptg = tid >> 3;   // 0..15 : points ptg*8 .. +7
    const int chg = tid & 7;    // 0..7  : channels chg*8 .. +7
    __syncthreads();

    for (int t = blockIdx.x; t < NTILE; t += PGRID) {
        const int base = t * BLK;
        const int pg = min(base + tid, NPTS - 1);
        float pd0 = pos[pg * 3 + 0];
        float pd1 = pos[pg * 3 + 1];
        float pd2 = pos[pg * 3 + 2];
        float fr[16];
        {
            const float4* fv = (const float4*)(feat + pg * 16);
#pragma unroll
            for (int i = 0; i < 4; ++i) {
                float4 q = fv[i];
                fr[4 * i + 0] = q.x; fr[4 * i + 1] = q.y;
                fr[4 * i + 2] = q.z; fr[4 * i + 3] = q.w;
            }
        }
        {
            float v1 = (ax1 == 0) ? pd0 : ((ax1 == 1) ? pd1 : pd2);
            float v2 = (ax2 == 0) ? pd0 : ((ax2 == 1) ? pd1 : pd2);
            float n1 = fminf(fmaxf((v1 + 1.0f) * 0.5f, 0.0f), 1.0f);
            float n2 = fminf(fmaxf((v2 + 1.0f) * 0.5f, 0.0f), 1.0f);
            int i1 = min(max((int)floorf(n1 * (float)GRID_H), 0), GRID_H - 1);
            int i2 = min(max((int)floorf(n2 * (float)GRID_W), 0), GRID_W - 1);
            sFlat[tid] = i1 * GRID_W + i2;
        }

        unsigned long long acc[8][4];   // [pt][chpair]
#pragma unroll
        for (int a = 0; a < 8; ++a)
#pragma unroll
            for (int b = 0; b < 4; ++b) acc[a][b] = 0ull;

        // ---- build X chunk 0 (k = 0..12: pure features) ----
#pragma unroll
        for (int i = 0; i < KC; ++i)
            *(float2*)&sm[OX0 + i * 256 + 2 * tid] = make_float2(fr[i], fr[i]);
        __syncthreads();

        // ================= GEMM1: 16 double-buffered chunks of K=13 ==========
#pragma unroll 1
        for (int c = 0; c < 16; ++c) {
            if (c < 15) {
                const int k0 = (c + 1) * KC;
                float* xb = &sm[((c + 1) & 1) ? OX1 : OX0];
#pragma unroll
                for (int i = 0; i < KC; ++i) {
                    int k = k0 + i;
                    float v;
                    if (k < 16) {
                        v = fr[k];
                    } else {
                        int j = k - 16;
                        float pdx = (j < 64) ? pd0 : ((j < 128) ? pd1 : pd2);
                        float2 mp = *(const float2*)&sm[OMP + 2 * (j & 63)];
                        v = __sinf(fmaf(pdx, mp.x, mp.y));
                    }
                    *(float2*)&xb[i * 256 + 2 * tid] = make_float2(v, v);
                }
            }
            const float* xc = &sm[(c & 1) ? OX1 : OX0];
            const int kb = c * KC;
#pragma unroll
            for (int i = 0; i < KC; ++i) {
                const float* xr = &xc[i * 256 + ptg * 16];
                ulonglong2 x0 = *(const ulonglong2*)xr;        // dup(p0), dup(p1)
                ulonglong2 x1 = *(const ulonglong2*)(xr + 4);  // dup(p2), dup(p3)
                ulonglong2 x2 = *(const ulonglong2*)(xr + 8);
                ulonglong2 x3 = *(const ulonglong2*)(xr + 12);
                unsigned long long xp[8] = {x0.x, x0.y, x1.x, x1.y,
                                            x2.x, x2.y, x3.x, x3.y};
                const float* wr = &sm[OW1 + (kb + i) * 64 + chg * 8];
                ulonglong2 wa = *(const ulonglong2*)wr;        // (c0,c1),(c2,c3)
                ulonglong2 wb = *(const ulonglong2*)(wr + 4);  // (c4,c5),(c6,c7)
                unsigned long long wp[4] = {wa.x, wa.y, wb.x, wb.y};
#pragma unroll
                for (int a = 0; a < 8; ++a)
#pragma unroll
                    for (int b = 0; b < 4; ++b) fma2(acc[a][b], xp[a], wp[b]);
            }
            __syncthreads();
        }

        // ---- write H = h + b1, layout [pt][ch] stride HP ----
        float bb[8];
#pragma unroll
        for (int j = 0; j < 8; ++j) bb[j] = sm[OB1 + chg * 8 + j];
#pragma unroll
        for (int a = 0; a < 8; ++a) {
            int pt = ptg * 8 + a;
            float2 t0 = up2(acc[a][0]), t1 = up2(acc[a][1]);
            float2 t2 = up2(acc[a][2]), t3 = up2(acc[a][3]);
            float4 o0 = {t0.x + bb[0], t0.y + bb[1], t1.x + bb[2], t1.y + bb[3]};
            float4 o1 = {t2.x + bb[4], t2.y + bb[5], t3.x + bb[6], t3.y + bb[7]};
            *(float4*)&sm[OH + pt * HP + chg * 8]     = o0;
            *(float4*)&sm[OH + pt * HP + chg * 8 + 4] = o1;
#pragma unroll
            for (int b = 0; b < 4; ++b) acc[a][b] = 0ull;
        }
        __syncthreads();

        // ---- LayerNorm + exact GELU: thread tid owns point tid ----
        {
            float v[64];
#pragma unroll
            for (int q = 0; q < 16; ++q) {
                float4 x = *(const float4*)&sm[OH + tid * HP + 4 * q];
                v[4 * q + 0] = x.x; v[4 * q + 1] = x.y;
                v[4 * q + 2] = x.z; v[4 * q + 3] = x.w;
            }
            float s = 0.0f, s2 = 0.0f;
#pragma unroll
            for (int c = 0; c < 64; ++c) { s += v[c]; s2 += v[c] * v[c]; }
            float mu = s * (1.0f / 64.0f);
            float var = s2 * (1.0f / 64.0f) - mu * mu;
            float rstd = rsqrtf(var + 1e-5f);
#pragma unroll
            for (int c = 0; c < 64; ++c) {
                float u = (v[c] - mu) * rstd * sm[OG + c] + sm[OB + c];
                v[c] = 0.5f * u * (1.0f + erff(u * 0.70710678118654752f));
            }
#pragma unroll
            for (int q = 0; q < 16; ++q) {
                float4 x = {v[4 * q], v[4 * q + 1], v[4 * q + 2], v[4 * q + 3]};
                *(float4*)&sm[OH + tid * HP + 4 * q] = x;
            }
        }
        __syncthreads();

        // ================= GEMM2: x from H [pt][ch] (scalar + dup MOV) =======
#pragma unroll 4
        for (int k = 0; k < 64; ++k) {
            unsigned long long xp[8];
#pragma unroll
            for (int a = 0; a < 8; ++a)
                xp[a] = dup2(sm[OH + (ptg * 8 + a) * HP + k]);
            const float* wr = &sm[OW2 + k * 64 + chg * 8];
            ulonglong2 wa = *(const ulonglong2*)wr;
            ulonglong2 wb = *(const ulonglong2*)(wr + 4);
            unsigned long long wp[4] = {wa.x, wa.y, wb.x, wb.y};
#pragma unroll
            for (int a = 0; a < 8; ++a)
#pragma unroll
                for (int b = 0; b < 4; ++b) fma2(acc[a][b], xp[a], wp[b]);
        }

        // ---- scatter: red.v4 into cell-major scratch ----
#pragma unroll
        for (int a = 0; a < 8; ++a) {
            int pl = ptg * 8 + a;
            if (base + pl < NPTS) {
                int fl = sFlat[pl];
                float* dst = &g_accum[fl * 64 + chg * 8];
                float2 t0 = up2(acc[a][0]), t1 = up2(acc[a][1]);
                float2 t2 = up2(acc[a][2]), t3 = up2(acc[a][3]);
                red4(dst,     t0.x + bb[0], t0.y + bb[1], t1.x + bb[2], t1.y + bb[3]);
                red4(dst + 4, t2.x + bb[4], t2.y + bb[5], t3.x + bb[6], t3.y + bb[7]);
                if (chg == 0) red1(&g_counts[fl], 1.0f);
            }
        }
        __syncthreads();   // protect H/X region before next tile's build
    }
}

// transpose [cell][ch] -> [ch][cell], mean-divide, re-zero scratch
__global__ __launch_bounds__(256)
void finalize_kernel(float* __restrict__ out) {
    __shared__ float tile[64][65];
    __shared__ float cnt[64];
    const int tid = threadIdx.x;
    const int cell0 = blockIdx.x * 64;

#pragma unroll
    for (int it = 0; it < 4; ++it) {
        int lin = it * 256 + tid;
        float4* src = (float4*)&g_accum[cell0 * 64] + lin;
        float4 v = *src;
        int row = lin >> 4, col4 = (lin & 15) * 4;
        tile[row][col4 + 0] = v.x;
        tile[row][col4 + 1] = v.y;
        tile[row][col4 + 2] = v.z;
        tile[row][col4 + 3] = v.w;
        *src = make_float4(0.0f, 0.0f, 0.0f, 0.0f);
    }
    if (tid < 64) {
        cnt[tid] = 1.0f / fmaxf(g_counts[cell0 + tid], 1.0f);
        g_counts[cell0 + tid] = 0.0f;
    }
    __syncthreads();

#pragma unroll
    for (int it = 0; it < 4; ++it) {
        int lin = it * 256 + tid;
        int ch = lin >> 4, cl4 = (lin & 15) * 4;
        float4 o;
        o.x = tile[cl4 + 0][ch] * cnt[cl4 + 0];
        o.y = tile[cl4 + 1][ch] * cnt[cl4 + 1];
        o.z = tile[cl4 + 2][ch] * cnt[cl4 + 2];
        o.w = tile[cl4 + 3][ch] * cnt[cl4 + 3];
        *(float4*)&out[ch * NCELL + cell0 + cl4] = o;
    }
}

extern "C" void kernel_launch(void* const* d_in, const int* in_sizes, int n_in,
                              void* d_out, int out_size) {
    const float* pos  = (const float*)d_in[0];
    const float* feat = (const float*)d_in[1];
    const float* W1   = (const float*)d_in[2];
    const float* b1   = (const float*)d_in[3];
    const float* lng  = (const float*)d_in[4];
    const float* lnb  = (const float*)d_in[5];
    const float* W2   = (const float*)d_in[6];
    const float* b2   = (const float*)d_in[7];
    const int*   ax1  = (const int*)d_in[8];
    const int*   ax2  = (const int*)d_in[9];
    float* out = (float*)d_out;

    cudaFuncSetAttribute(p2g_kernel, cudaFuncAttributeMaxDynamicSharedMemorySize, SMB);

    // scratch zeroed at load; finalize re-zeroes each call (no zero pass).
    // Launch pattern keeps p2g at the ncu-captured slot.
    p2g_kernel<<<PGRID, NTH, SMB>>>(pos, feat, W1, b1, lng, lnb, W2, b2, ax1, ax2);
    finalize_kernel<<<NCELL / 64, 256>>>(out);
    dummy_kernel<<<1, 32>>>();
}

// round 16
// speedup vs baseline: 3.4274x; 1.0358x over previous
#include <cuda_runtime.h>
#include <cuda_bf16.h>

#define NPTS    500000
#define C_OUT   64
#define GRID_H  256
#define GRID_W  256
#define NCELL   (GRID_H * GRID_W)
#define BLK     128                 // points per CTA
#define NTH     128
#define NTILE   3907                // ceil(500000 / 128)
#define PGRID   296                 // 2 CTAs per SM, persistent
#define KC      13                  // 16 chunks * 13 = 208

// shared float offsets
#define OW1  0            // 208*64 = 13312
#define OW2  13312        // 64*64  = 4096
#define OX0  17408        // 13*256 = 3328 (X dup'd pairs, buffer 0)
#define OX1  20736        // buffer 1
#define OB1  24064
#define OG   24128
#define OB   24192
#define OB2  24256
#define OMP  24320        // 64 float2 (freq, phase) = 128
#define OFL  24448        // 128 ints
#define SMF  24576
#define SMB  (SMF * 4)    // 98304 B -> 2 CTAs/SM

__device__ float g_accum[NCELL * C_OUT];   // cell-major scratch [cell][ch]
__device__ float g_counts[NCELL];

__device__ __forceinline__ void fma2(unsigned long long& d, unsigned long long a,
                                     unsigned long long b) {
    asm("fma.rn.f32x2 %0, %1, %2, %0;" : "+l"(d) : "l"(a), "l"(b));
}
__device__ __forceinline__ unsigned long long dup2(float v) {
    unsigned long long r; asm("mov.b64 %0, {%1, %1};" : "=l"(r) : "f"(v)); return r;
}
__device__ __forceinline__ unsigned long long pk(float x, float y) {
    unsigned long long r; asm("mov.b64 %0, {%1, %2};" : "=l"(r) : "f"(x), "f"(y)); return r;
}
__device__ __forceinline__ float2 up2(unsigned long long a) {
    float2 r; asm("mov.b64 {%0, %1}, %2;" : "=f"(r.x), "=f"(r.y) : "l"(a)); return r;
}
__device__ __forceinline__ void red4(float* p, float a, float b, float c, float d) {
    asm volatile("red.global.add.v4.f32 [%0], {%1, %2, %3, %4};"
                 :: "l"(p), "f"(a), "f"(b), "f"(c), "f"(d) : "memory");
}
__device__ __forceinline__ void red1(float* p, float v) {
    asm volatile("red.global.add.f32 [%0], %1;" :: "l"(p), "f"(v) : "memory");
}

__global__ void dummy_kernel() {}

__global__ __launch_bounds__(NTH)
void p2g_kernel(const float* __restrict__ pos,
                const float* __restrict__ feat,
                const float* __restrict__ W1,
                const float* __restrict__ b1,
                const float* __restrict__ lng,
                const float* __restrict__ lnb,
                const float* __restrict__ W2,
                const float* __restrict__ b2,
                const int*   __restrict__ ax1p,
                const int*   __restrict__ ax2p) {
    extern __shared__ float sm[];
    int* sFlat = (int*)&sm[OFL];
    const int tid = threadIdx.x;
    const int lid = tid & 31;

    // ---- stage weights + tables once (persistent CTA) ----
    {
        const float4* w1v = (const float4*)W1;
        float4* d1 = (float4*)&sm[OW1];
#pragma unroll
        for (int i = 0; i < 26; ++i) d1[tid + i * NTH] = w1v[tid + i * NTH];
        const float4* w2v = (const float4*)W2;
        float4* d2 = (float4*)&sm[OW2];
#pragma unroll
        for (int i = 0; i < 8; ++i) d2[tid + i * NTH] = w2v[tid + i * NTH];
        if (tid < 64) {
            int f = tid & 31, t = tid >> 5;
            sm[OMP + 2 * tid]     = exp2f((float)f * 0.03125f) * 1.57079632679489662f;
            sm[OMP + 2 * tid + 1] = t ? 1.57079632679489662f : 0.0f;
            sm[OB1 + tid] = b1[tid];
            sm[OG  + tid] = lng[tid];
            sm[OB  + tid] = lnb[tid];
            sm[OB2 + tid] = b2[tid];
        }
    }
    const int ax1 = *ax1p, ax2 = *ax2p;

    const int ptg = tid >> 3;   // 0..15 : points ptg*8 .. +7
    const int chg = tid & 7;    // 0..7  : channels chg*8 .. +7
    __syncthreads();

    // per-thread LN constants for its 8 channels (loop-invariant)
    float bb1[8], gl[8], blv[8], bb2[8];
#pragma unroll
    for (int j = 0; j < 8; ++j) {
        bb1[j] = sm[OB1 + chg * 8 + j];
        gl[j]  = sm[OG  + chg * 8 + j];
        blv[j] = sm[OB  + chg * 8 + j];
        bb2[j] = sm[OB2 + chg * 8 + j];
    }

    for (int t = blockIdx.x; t < NTILE; t += PGRID) {
        const int base = t * BLK;
        const int pg = min(base + tid, NPTS - 1);
        float pd0 = pos[pg * 3 + 0];
        float pd1 = pos[pg * 3 + 1];
        float pd2 = pos[pg * 3 + 2];
        float fr[16];
        {
            const float4* fv = (const float4*)(feat + pg * 16);
#pragma unroll
            for (int i = 0; i < 4; ++i) {
                float4 q = fv[i];
                fr[4 * i + 0] = q.x; fr[4 * i + 1] = q.y;
                fr[4 * i + 2] = q.z; fr[4 * i + 3] = q.w;
            }
        }
        {
            float v1 = (ax1 == 0) ? pd0 : ((ax1 == 1) ? pd1 : pd2);
            float v2 = (ax2 == 0) ? pd0 : ((ax2 == 1) ? pd1 : pd2);
            float n1 = fminf(fmaxf((v1 + 1.0f) * 0.5f, 0.0f), 1.0f);
            float n2 = fminf(fmaxf((v2 + 1.0f) * 0.5f, 0.0f), 1.0f);
            int i1 = min(max((int)floorf(n1 * (float)GRID_H), 0), GRID_H - 1);
            int i2 = min(max((int)floorf(n2 * (float)GRID_W), 0), GRID_W - 1);
            sFlat[tid] = i1 * GRID_W + i2;
        }

        unsigned long long acc[8][4];   // [pt][chpair]
#pragma unroll
        for (int a = 0; a < 8; ++a)
#pragma unroll
            for (int b = 0; b < 4; ++b) acc[a][b] = 0ull;

        // ---- build X chunk 0 (k = 0..12: pure features) ----
#pragma unroll
        for (int i = 0; i < KC; ++i)
            *(float2*)&sm[OX0 + i * 256 + 2 * tid] = make_float2(fr[i], fr[i]);
        __syncthreads();

        // ================= GEMM1: 16 double-buffered chunks of K=13 ==========
#pragma unroll 1
        for (int c = 0; c < 16; ++c) {
            if (c < 15) {
                const int k0 = (c + 1) * KC;
                float* xb = &sm[((c + 1) & 1) ? OX1 : OX0];
#pragma unroll
                for (int i = 0; i < KC; ++i) {
                    int k = k0 + i;
                    float v;
                    if (k < 16) {
                        v = fr[k];
                    } else {
                        int j = k - 16;
                        float pdx = (j < 64) ? pd0 : ((j < 128) ? pd1 : pd2);
                        float2 mp = *(const float2*)&sm[OMP + 2 * (j & 63)];
                        v = __sinf(fmaf(pdx, mp.x, mp.y));
                    }
                    *(float2*)&xb[i * 256 + 2 * tid] = make_float2(v, v);
                }
            }
            const float* xc = &sm[(c & 1) ? OX1 : OX0];
            const int kb = c * KC;
#pragma unroll
            for (int i = 0; i < KC; ++i) {
                const float* xr = &xc[i * 256 + ptg * 16];
                ulonglong2 x0 = *(const ulonglong2*)xr;        // dup(p0), dup(p1)
                ulonglong2 x1 = *(const ulonglong2*)(xr + 4);
                ulonglong2 x2 = *(const ulonglong2*)(xr + 8);
                ulonglong2 x3 = *(const ulonglong2*)(xr + 12);
                unsigned long long xp[8] = {x0.x, x0.y, x1.x, x1.y,
                                            x2.x, x2.y, x3.x, x3.y};
                const float* wr = &sm[OW1 + (kb + i) * 64 + chg * 8];
                ulonglong2 wa = *(const ulonglong2*)wr;
                ulonglong2 wb = *(const ulonglong2*)(wr + 4);
                unsigned long long wp[4] = {wa.x, wa.y, wb.x, wb.y};
#pragma unroll
                for (int a = 0; a < 8; ++a)
#pragma unroll
                    for (int b = 0; b < 4; ++b) fma2(acc[a][b], xp[a], wp[b]);
            }
            __syncthreads();
        }

        // ---- bias + LayerNorm (8-lane shfl) + exact GELU, all in registers --
        {
            float s[8], s2[8];
#pragma unroll
            for (int a = 0; a < 8; ++a) {
                s[a] = 0.0f; s2[a] = 0.0f;
#pragma unroll
                for (int cp = 0; cp < 4; ++cp) {
                    float2 v = up2(acc[a][cp]);
                    v.x += bb1[2 * cp];
                    v.y += bb1[2 * cp + 1];
                    s[a]  += v.x + v.y;
                    s2[a] += v.x * v.x + v.y * v.y;
                    acc[a][cp] = pk(v.x, v.y);
                }
            }
#pragma unroll
            for (int o = 1; o < 8; o <<= 1) {
#pragma unroll
                for (int a = 0; a < 8; ++a) {
                    s[a]  += __shfl_xor_sync(0xFFFFFFFF, s[a],  o);
                    s2[a] += __shfl_xor_sync(0xFFFFFFFF, s2[a], o);
                }
            }
#pragma unroll
            for (int a = 0; a < 8; ++a) {
                float mu   = s[a] * (1.0f / 64.0f);
                float var  = s2[a] * (1.0f / 64.0f) - mu * mu;
                float rstd = rsqrtf(var + 1e-5f);
#pragma unroll
                for (int cp = 0; cp < 4; ++cp) {
                    float2 v = up2(acc[a][cp]);
                    float ux = (v.x - mu) * rstd * gl[2 * cp]     + blv[2 * cp];
                    float uy = (v.y - mu) * rstd * gl[2 * cp + 1] + blv[2 * cp + 1];
                    ux = 0.5f * ux * (1.0f + erff(ux * 0.70710678118654752f));
                    uy = 0.5f * uy * (1.0f + erff(uy * 0.70710678118654752f));
                    acc[a][cp] = pk(ux, uy);
                }
            }
        }

        // ================= GEMM2: x via warp shuffle (no smem H) =============
        unsigned long long a2[8][4];
#pragma unroll
        for (int a = 0; a < 8; ++a)
#pragma unroll
            for (int b = 0; b < 4; ++b) a2[a][b] = 0ull;

        const int srcBase = lid & 0x18;   // warp-local ptg group base lane
#pragma unroll
        for (int k = 0; k < 64; ++k) {
            const int src = srcBase | (k >> 3);
            unsigned long long xp[8];
#pragma unroll
            for (int a = 0; a < 8; ++a) {
                float2 tv = up2(acc[a][(k & 7) >> 1]);
                float v = (k & 1) ? tv.y : tv.x;
                xp[a] = dup2(__shfl_sync(0xFFFFFFFF, v, src));
            }
            const float* wr = &sm[OW2 + k * 64 + chg * 8];
            ulonglong2 wa = *(const ulonglong2*)wr;
            ulonglong2 wb = *(const ulonglong2*)(wr + 4);
            unsigned long long wp[4] = {wa.x, wa.y, wb.x, wb.y};
#pragma unroll
            for (int a = 0; a < 8; ++a)
#pragma unroll
                for (int b = 0; b < 4; ++b) fma2(a2[a][b], xp[a], wp[b]);
        }

        // ---- scatter: red.v4 into cell-major scratch ----
#pragma unroll
        for (int a = 0; a < 8; ++a) {
            int pl = ptg * 8 + a;
            if (base + pl < NPTS) {
                int fl = sFlat[pl];
                float* dst = &g_accum[fl * 64 + chg * 8];
                float2 t0 = up2(a2[a][0]), t1 = up2(a2[a][1]);
                float2 t2 = up2(a2[a][2]), t3 = up2(a2[a][3]);
                red4(dst,     t0.x + bb2[0], t0.y + bb2[1], t1.x + bb2[2], t1.y + bb2[3]);
                red4(dst + 4, t2.x + bb2[4], t2.y + bb2[5], t3.x + bb2[6], t3.y + bb2[7]);
                if (chg == 0) red1(&g_counts[fl], 1.0f);
            }
        }
        __syncthreads();   // protect X buffers / sFlat before next tile
    }
}

// transpose [cell][ch] -> [ch][cell], mean-divide, re-zero scratch
__global__ __launch_bounds__(256)
void finalize_kernel(float* __restrict__ out) {
    __shared__ float tile[64][65];
    __shared__ float cnt[64];
    const int tid = threadIdx.x;
    const int cell0 = blockIdx.x * 64;

#pragma unroll
    for (int it = 0; it < 4; ++it) {
        int lin = it * 256 + tid;
        float4* src = (float4*)&g_accum[cell0 * 64] + lin;
        float4 v = *src;
        int row = lin >> 4, col4 = (lin & 15) * 4;
        tile[row][col4 + 0] = v.x;
        tile[row][col4 + 1] = v.y;
        tile[row][col4 + 2] = v.z;
        tile[row][col4 + 3] = v.w;
        *src = make_float4(0.0f, 0.0f, 0.0f, 0.0f);
    }
    if (tid < 64) {
        cnt[tid] = 1.0f / fmaxf(g_counts[cell0 + tid], 1.0f);
        g_counts[cell0 + tid] = 0.0f;
    }
    __syncthreads();

#pragma unroll
    for (int it = 0; it < 4; ++it) {
        int lin = it * 256 + tid;
        int ch = lin >> 4, cl4 = (lin & 15) * 4;
        float4 o;
        o.x = tile[cl4 + 0][ch] * cnt[cl4 + 0];
        o.y = tile[cl4 + 1][ch] * cnt[cl4 + 1];
        o.z = tile[cl4 + 2][ch] * cnt[cl4 + 2];
        o.w = tile[cl4 + 3][ch] * cnt[cl4 + 3];
        *(float4*)&out[ch * NCELL + cell0 + cl4] = o;
    }
}

extern "C" void kernel_launch(void* const* d_in, const int* in_sizes, int n_in,
                              void* d_out, int out_size) {
    const float* pos  = (const float*)d_in[0];
    const float* feat = (const float*)d_in[1];
    const float* W1   = (const float*)d_in[2];
    const float* b1   = (const float*)d_in[3];
    const float* lng  = (const float*)d_in[4];
    const float* lnb  = (const float*)d_in[5];
    const float* W2   = (const float*)d_in[6];
    const float* b2   = (const float*)d_in[7];
    const int*   ax1  = (const int*)d_in[8];
    const int*   ax2  = (const int*)d_in[9];
    float* out = (float*)d_out;

    cudaFuncSetAttribute(p2g_kernel, cudaFuncAttributeMaxDynamicSharedMemorySize, SMB);

    // scratch zeroed at load; finalize re-zeroes each call (no zero pass).
    // Launch pattern keeps p2g at the ncu-captured slot.
    p2g_kernel<<<PGRID, NTH, SMB>>>(pos, feat, W1, b1, lng, lnb, W2, b2, ax1, ax2);
    finalize_kernel<<<NCELL / 64, 256>>>(out);
    dummy_kernel<<<1, 32>>>();
}